// round 5
// baseline (speedup 1.0000x reference)
#include <cuda_runtime.h>
#include <cstdint>

#define CL 4096
#define CS 4096
#define CE 768
#define CH 12
#define CD 64

#define QSTR 68   // Q/K row stride (words): row-step ≡ 4 mod 32 banks
#define VSTR 72   // V row stride (words): row-step ≡ 8 mod 32 banks
#define ASTR 36   // gemm A tile stride
#define WSTR 72   // gemm W tile stride

static __device__ __host__ constexpr float INV_SCALE = 0.036084391824351614f; // 1/sqrt(768)

__device__ float g_Q[CL * CE];
__device__ float g_K[CS * CE];
__device__ float g_V[CS * CE];
__device__ float g_O[CL * CE];
__device__ uint32_t g_MB[(size_t)CL * CS / 32];

// ---------------------------------------------------------------------------
__device__ __forceinline__ float to_tf32(float x) {
    uint32_t u;
    asm("cvt.rna.tf32.f32 %0, %1;" : "=r"(u) : "f"(x));
    return __uint_as_float(u);
}

__device__ __forceinline__ void mma_tf32(float c[4], float a0, float a1,
                                         float a2, float a3, float b0, float b1) {
    asm volatile(
        "mma.sync.aligned.m16n8k8.row.col.f32.tf32.tf32.f32 "
        "{%0,%1,%2,%3}, {%4,%5,%6,%7}, {%8,%9}, {%0,%1,%2,%3};\n"
        : "+f"(c[0]), "+f"(c[1]), "+f"(c[2]), "+f"(c[3])
        : "r"(__float_as_uint(a0)), "r"(__float_as_uint(a1)),
          "r"(__float_as_uint(a2)), "r"(__float_as_uint(a3)),
          "r"(__float_as_uint(b0)), "r"(__float_as_uint(b1)));
}

__device__ __forceinline__ uint32_t s2u(const void* p) {
    return (uint32_t)__cvta_generic_to_shared(p);
}
__device__ __forceinline__ void cpa(uint32_t d, const void* s) {
    asm volatile("cp.async.cg.shared.global [%0], [%1], 16;" :: "r"(d), "l"(s));
}
__device__ __forceinline__ void cpcommit() {
    asm volatile("cp.async.commit_group;");
}
template <int N> __device__ __forceinline__ void cpwait() {
    asm volatile("cp.async.wait_group %0;" :: "n"(N));
}

// ---------------------------------------------------------------------------
// Pack mask to bits, vectorized: bit i of word w = mask[w*32+i] != 0
// ---------------------------------------------------------------------------
__global__ __launch_bounds__(256) void pack_mask(const int* __restrict__ m,
                                                 uint32_t* __restrict__ mb) {
    __shared__ uint32_t nib[256];
    int t = threadIdx.x;
    size_t base = (size_t)blockIdx.x * 1024 + (size_t)t * 4;
    int4 v = *(const int4*)&m[base];
    nib[t] = (v.x ? 1u : 0u) | (v.y ? 2u : 0u) | (v.z ? 4u : 0u) | (v.w ? 8u : 0u);
    __syncthreads();
    if (t < 32) {
        uint32_t w = 0;
#pragma unroll
        for (int j = 0; j < 8; j++) w |= nib[t * 8 + j] << (4 * j);
        mb[(size_t)blockIdx.x * 32 + t] = w;
    }
}

// ---------------------------------------------------------------------------
// tf32 GEMM core, cp.async double-buffered. 256 thr (8 warps x 16 rows),
// CTA tile 128x64, k-step 32. C = (A@W)*scale (+bias) [opt round->tf32].
// ---------------------------------------------------------------------------
__device__ __forceinline__ void gemm_body(const float* __restrict__ A,
                                          const float* __restrict__ W,
                                          const float* __restrict__ bias,
                                          float* __restrict__ C,
                                          int M, int N, int K,
                                          float scale, int do_round,
                                          int m0, int n0, float* sg)
{
    float* smA = sg;                       // 2 x 128 x ASTR
    float* smW = sg + 2 * 128 * ASTR;      // 2 x 32 x WSTR

    const int tid = threadIdx.x;
    const int wid = tid >> 5;
    const int ln  = tid & 31;
    const int gid = ln >> 2;
    const int tig = ln & 3;
    const int qb  = wid * 16;

    auto issue = [&](int k0, int b) {
        float* dA = smA + b * 128 * ASTR;
        float* dW = smW + b * 32 * WSTR;
#pragma unroll
        for (int i = 0; i < 4; i++) {
            int lin = tid + i * 256;
            int row = lin >> 3;
            int c4 = (lin & 7) << 2;
            cpa(s2u(&dA[row * ASTR + c4]), &A[(size_t)(m0 + row) * K + k0 + c4]);
        }
#pragma unroll
        for (int i = 0; i < 2; i++) {
            int lin = tid + i * 256;
            int kr = lin >> 4;
            int c4 = (lin & 15) << 2;
            cpa(s2u(&dW[kr * WSTR + c4]), &W[(size_t)(k0 + kr) * N + n0 + c4]);
        }
        cpcommit();
    };

    float c[8][4];
#pragma unroll
    for (int nf = 0; nf < 8; nf++)
#pragma unroll
        for (int j = 0; j < 4; j++) c[nf][j] = 0.f;

    const int NS = K / 32;  // 24
    issue(0, 0);
    issue(32, 1);

    for (int ks = 0; ks < NS; ks++) {
        const int buf = ks & 1;
        if (ks < NS - 1) cpwait<1>(); else cpwait<0>();
        __syncthreads();

        const float* Ab = smA + buf * 128 * ASTR;
        const float* Wb = smW + buf * 32 * WSTR;

#pragma unroll
        for (int kk = 0; kk < 4; kk++) {
            float a[4];
            int base = (qb + gid) * ASTR + kk * 8 + tig;
            a[0] = to_tf32(Ab[base]);
            a[1] = to_tf32(Ab[base + 8 * ASTR]);
            a[2] = to_tf32(Ab[base + 4]);
            a[3] = to_tf32(Ab[base + 8 * ASTR + 4]);
#pragma unroll
            for (int nf = 0; nf < 8; nf++) {
                float b0 = to_tf32(Wb[(kk * 8 + tig) * WSTR + nf * 8 + gid]);
                float b1 = to_tf32(Wb[(kk * 8 + tig + 4) * WSTR + nf * 8 + gid]);
                mma_tf32(c[nf], a[0], a[1], a[2], a[3], b0, b1);
            }
        }
        __syncthreads();
        if (ks + 2 < NS) issue((ks + 2) * 32, buf);
    }

    const int r0 = m0 + qb + gid;
    const int r1 = r0 + 8;
#pragma unroll
    for (int nf = 0; nf < 8; nf++) {
        int n = n0 + nf * 8 + 2 * tig;
        float v0 = c[nf][0] * scale, v1 = c[nf][1] * scale;
        float v2 = c[nf][2] * scale, v3 = c[nf][3] * scale;
        if (bias) { v0 += bias[n]; v1 += bias[n + 1]; v2 += bias[n]; v3 += bias[n + 1]; }
        if (do_round) {
            v0 = to_tf32(v0); v1 = to_tf32(v1);
            v2 = to_tf32(v2); v3 = to_tf32(v3);
        }
        *(float2*)&C[(size_t)r0 * N + n] = make_float2(v0, v1);
        *(float2*)&C[(size_t)r1 * N + n] = make_float2(v2, v3);
    }
}

// Fused 3-way projection: grid.z selects (input, weight, output, scale).
__global__ __launch_bounds__(256) void gemm_proj(const float* __restrict__ q_in,
                                                 const float* __restrict__ k_in,
                                                 const float* __restrict__ v_in,
                                                 const float* __restrict__ Wq,
                                                 const float* __restrict__ Wk,
                                                 const float* __restrict__ Wv,
                                                 float* __restrict__ Qp,
                                                 float* __restrict__ Kp,
                                                 float* __restrict__ Vp)
{
    extern __shared__ float sg[];
    const int z = blockIdx.z;
    const float* A = (z == 0) ? q_in : (z == 1) ? k_in : v_in;
    const float* W = (z == 0) ? Wq : (z == 1) ? Wk : Wv;
    float* C = (z == 0) ? Qp : (z == 1) ? Kp : Vp;
    float scale = (z == 0) ? INV_SCALE : 1.0f;
    gemm_body(A, W, nullptr, C, CL, CE, CE, scale, 1,
              blockIdx.y * 128, blockIdx.x * 64, sg);
}

__global__ __launch_bounds__(256) void gemm_out(const float* __restrict__ A,
                                                const float* __restrict__ W,
                                                const float* __restrict__ bias,
                                                float* __restrict__ C)
{
    extern __shared__ float sg[];
    gemm_body(A, W, bias, C, CL, CE, CE, 1.0f, 0,
              blockIdx.y * 128, blockIdx.x * 64, sg);
}

// ---------------------------------------------------------------------------
// Flash attention, cp.async double-buffered K/V, shuffle-based P redistribution.
// Block = (128 q, head), 8 warps x 16 rows. Q/K/V already tf32-rounded,
// Q already scaled by 1/sqrt(E).
// ---------------------------------------------------------------------------
__global__ __launch_bounds__(256) void flash_tc(const float* __restrict__ Qg,
                                                const float* __restrict__ Kg,
                                                const float* __restrict__ Vg,
                                                const uint32_t* __restrict__ MBg,
                                                float* __restrict__ Og)
{
    extern __shared__ float smx[];
    float* Qs = smx;                        // 128 x QSTR
    float* Ks = Qs + 128 * QSTR;            // 2 x 64 x QSTR
    float* Vs = Ks + 2 * 64 * QSTR;         // 2 x 64 x VSTR

    const uint2* MB2 = (const uint2*)MBg;

    const int h  = blockIdx.y;
    const int q0 = blockIdx.x * 128;
    const int tid = threadIdx.x;
    const int wid = tid >> 5;
    const int ln  = tid & 31;
    const int gid = ln >> 2;
    const int tig = ln & 3;
    const int qb = wid * 16;

    auto issueKV = [&](int k0, int b) {
        float* dK = Ks + b * 64 * QSTR;
        float* dV = Vs + b * 64 * VSTR;
#pragma unroll
        for (int i = 0; i < 4; i++) {
            int lin = tid + i * 256;
            int row = lin >> 4;
            int c4 = (lin & 15) << 2;
            cpa(s2u(&dK[row * QSTR + c4]), &Kg[(size_t)(k0 + row) * CE + h * CD + c4]);
            cpa(s2u(&dV[row * VSTR + c4]), &Vg[(size_t)(k0 + row) * CE + h * CD + c4]);
        }
        cpcommit();
    };

    // prologue: Q + KV tile0 (group 0), KV tile1 (group 1)
#pragma unroll
    for (int i = 0; i < 8; i++) {
        int lin = tid + i * 256;
        int row = lin >> 4;
        int c4 = (lin & 15) << 2;
        cpa(s2u(&Qs[row * QSTR + c4]), &Qg[(size_t)(q0 + row) * CE + h * CD + c4]);
    }
    issueKV(0, 0);
    issueKV(64, 1);

    float m_i[2] = {-1e30f, -1e30f};
    float l_i[2] = {0.f, 0.f};
    float o[8][4];
#pragma unroll
    for (int nf = 0; nf < 8; nf++)
#pragma unroll
        for (int j = 0; j < 4; j++) o[nf][j] = 0.f;

    const int mrow = q0 + qb + gid;
    const int NT = CS / 64;  // 64

    for (int t = 0; t < NT; t++) {
        const int buf = t & 1;

        // mask bits for this tile (independent of smem)
        uint2 mw0 = MB2[(size_t)mrow * 64 + t];
        uint2 mw1 = MB2[(size_t)(mrow + 8) * 64 + t];

        if (t < NT - 1) cpwait<1>(); else cpwait<0>();
        __syncthreads();

        const float* Kb = Ks + buf * 64 * QSTR;
        const float* Vb = Vs + buf * 64 * VSTR;

        // S = Q @ K^T  (warp: 16 x 64)
        float s[8][4];
#pragma unroll
        for (int nf = 0; nf < 8; nf++)
#pragma unroll
            for (int j = 0; j < 4; j++) s[nf][j] = 0.f;

#pragma unroll
        for (int kk = 0; kk < 8; kk++) {
            float a[4];
            int base = (qb + gid) * QSTR + kk * 8 + tig;
            a[0] = Qs[base];
            a[1] = Qs[base + 8 * QSTR];
            a[2] = Qs[base + 4];
            a[3] = Qs[base + 8 * QSTR + 4];
#pragma unroll
            for (int nf = 0; nf < 8; nf++) {
                float b0 = Kb[(nf * 8 + gid) * QSTR + kk * 8 + tig];
                float b1 = Kb[(nf * 8 + gid) * QSTR + kk * 8 + tig + 4];
                mma_tf32(s[nf], a[0], a[1], a[2], a[3], b0, b1);
            }
        }

        // online softmax + mask
        {
            float mx0 = -1e30f, mx1 = -1e30f;
#pragma unroll
            for (int nf = 0; nf < 8; nf++) {
                mx0 = fmaxf(mx0, fmaxf(s[nf][0], s[nf][1]));
                mx1 = fmaxf(mx1, fmaxf(s[nf][2], s[nf][3]));
            }
#pragma unroll
            for (int off = 1; off <= 2; off <<= 1) {
                mx0 = fmaxf(mx0, __shfl_xor_sync(0xffffffffu, mx0, off));
                mx1 = fmaxf(mx1, __shfl_xor_sync(0xffffffffu, mx1, off));
            }
            float mn0 = fmaxf(m_i[0], mx0);
            float mn1 = fmaxf(m_i[1], mx1);
            float cr0 = __expf(m_i[0] - mn0);
            float cr1 = __expf(m_i[1] - mn1);

            float sum0 = 0.f, sum1 = 0.f;
#pragma unroll
            for (int nf = 0; nf < 8; nf++) {
                uint32_t w0 = (nf < 4) ? mw0.x : mw0.y;
                uint32_t w1 = (nf < 4) ? mw1.x : mw1.y;
                int sh = ((nf & 3) << 3) + 2 * tig;
                float p0 = __expf(s[nf][0] - mn0);
                float p1 = __expf(s[nf][1] - mn0);
                float p2 = __expf(s[nf][2] - mn1);
                float p3 = __expf(s[nf][3] - mn1);
                p0 = ((w0 >> sh) & 1) ? p0 : 0.f;
                p1 = ((w0 >> (sh + 1)) & 1) ? p1 : 0.f;
                p2 = ((w1 >> sh) & 1) ? p2 : 0.f;
                p3 = ((w1 >> (sh + 1)) & 1) ? p3 : 0.f;
                s[nf][0] = p0; s[nf][1] = p1;
                s[nf][2] = p2; s[nf][3] = p3;
                sum0 += p0 + p1;
                sum1 += p2 + p3;
            }
#pragma unroll
            for (int off = 1; off <= 2; off <<= 1) {
                sum0 += __shfl_xor_sync(0xffffffffu, sum0, off);
                sum1 += __shfl_xor_sync(0xffffffffu, sum1, off);
            }
            l_i[0] = l_i[0] * cr0 + sum0;
            l_i[1] = l_i[1] * cr1 + sum1;
            m_i[0] = mn0;
            m_i[1] = mn1;
#pragma unroll
            for (int nf = 0; nf < 8; nf++) {
                o[nf][0] *= cr0; o[nf][1] *= cr0;
                o[nf][2] *= cr1; o[nf][3] *= cr1;
            }
        }

        // O += P @ V : A-frags built from S C-frags via lane shuffles
        const int srcA = 4 * gid + (tig >> 1);
        const int srcB = srcA + 2;
        const bool odd = (tig & 1);
#pragma unroll
        for (int g = 0; g < 8; g++) {
            float a[4];
            float x0 = __shfl_sync(0xffffffffu, s[g][0], srcA);
            float x1 = __shfl_sync(0xffffffffu, s[g][1], srcA);
            float y0 = __shfl_sync(0xffffffffu, s[g][2], srcA);
            float y1 = __shfl_sync(0xffffffffu, s[g][3], srcA);
            float x2 = __shfl_sync(0xffffffffu, s[g][0], srcB);
            float x3 = __shfl_sync(0xffffffffu, s[g][1], srcB);
            float y2 = __shfl_sync(0xffffffffu, s[g][2], srcB);
            float y3 = __shfl_sync(0xffffffffu, s[g][3], srcB);
            a[0] = to_tf32(odd ? x1 : x0);
            a[1] = to_tf32(odd ? y1 : y0);
            a[2] = to_tf32(odd ? x3 : x2);
            a[3] = to_tf32(odd ? y3 : y2);
#pragma unroll
            for (int nf = 0; nf < 8; nf++) {
                float b0 = Vb[(g * 8 + tig) * VSTR + nf * 8 + gid];
                float b1 = Vb[(g * 8 + tig + 4) * VSTR + nf * 8 + gid];
                mma_tf32(o[nf], a[0], a[1], a[2], a[3], b0, b1);
            }
        }

        __syncthreads();
        if (t + 2 < NT) issueKV((t + 2) * 64, buf);
    }

    // epilogue
    float inv0 = (l_i[0] > 0.f) ? (1.f / l_i[0]) : 0.f;
    float inv1 = (l_i[1] > 0.f) ? (1.f / l_i[1]) : 0.f;
    const int r0 = q0 + qb + gid;
#pragma unroll
    for (int nf = 0; nf < 8; nf++) {
        int cc = h * CD + nf * 8 + 2 * tig;
        *(float2*)&Og[(size_t)r0 * CE + cc] =
            make_float2(o[nf][0] * inv0, o[nf][1] * inv0);
        *(float2*)&Og[(size_t)(r0 + 8) * CE + cc] =
            make_float2(o[nf][2] * inv1, o[nf][3] * inv1);
    }
}

// ---------------------------------------------------------------------------

extern "C" void kernel_launch(void* const* d_in, const int* in_sizes, int n_in,
                              void* d_out, int out_size)
{
    const float* query = (const float*)d_in[0];
    const float* key   = (const float*)d_in[1];
    const float* value = (const float*)d_in[2];
    const int*   mask  = (const int*)d_in[3];
    const float* Wq    = (const float*)d_in[4];
    const float* Wk    = (const float*)d_in[5];
    const float* Wv    = (const float*)d_in[6];
    const float* Wo    = (const float*)d_in[7];
    const float* bo    = (const float*)d_in[8];
    float* out = (float*)d_out;

    float *Qp, *Kp, *Vp, *Op;
    uint32_t* MBp;
    cudaGetSymbolAddress((void**)&Qp, g_Q);
    cudaGetSymbolAddress((void**)&Kp, g_K);
    cudaGetSymbolAddress((void**)&Vp, g_V);
    cudaGetSymbolAddress((void**)&Op, g_O);
    cudaGetSymbolAddress((void**)&MBp, g_MB);

    const int gemm_smem = (2 * 128 * ASTR + 2 * 32 * WSTR) * (int)sizeof(float);   // 55296
    const int flash_smem = (128 * QSTR + 2 * 64 * QSTR + 2 * 64 * VSTR) * (int)sizeof(float); // 106496

    cudaFuncSetAttribute(gemm_proj, cudaFuncAttributeMaxDynamicSharedMemorySize, gemm_smem);
    cudaFuncSetAttribute(gemm_out, cudaFuncAttributeMaxDynamicSharedMemorySize, gemm_smem);
    cudaFuncSetAttribute(flash_tc, cudaFuncAttributeMaxDynamicSharedMemorySize, flash_smem);

    dim3 blk(256);

    pack_mask<<<(CL * CS) / 1024, 256>>>(mask, MBp);

    gemm_proj<<<dim3(CE / 64, CL / 128, 3), blk, gemm_smem>>>(
        query, key, value, Wq, Wk, Wv, Qp, Kp, Vp);

    flash_tc<<<dim3(CL / 128, CH), blk, flash_smem>>>(Qp, Kp, Vp, MBp, Op);

    gemm_out<<<dim3(CE / 64, CL / 128), blk, gemm_smem>>>(Op, Wo, bo, out);
}

// round 6
// speedup vs baseline: 1.8046x; 1.8046x over previous
#include <cuda_runtime.h>
#include <cuda_fp16.h>
#include <cstdint>

#define CL 4096
#define CS 4096
#define CE 768
#define CH 12
#define CD 64
#define HSTR 72   // half-row stride: 144B -> 16B-aligned rows, bank-quad pattern 0,4,..28

static __device__ __host__ constexpr float INV_SCALE = 0.036084391824351614f; // 1/sqrt(768)

// Scratch (no cudaMalloc allowed)
__device__ __half g_Q[CL * CE];
__device__ __half g_K[CS * CE];
__device__ __half g_V[CS * CE];
__device__ __half g_O[CL * CE];
__device__ __half g_X[(size_t)CL * CE * 3];  // fp16 inputs q,k,v
__device__ __half g_W[(size_t)CE * CE * 4];  // fp16 weights Wq,Wk,Wv,Wo
__device__ uint32_t g_MB[(size_t)CL * CS / 32];

// ---------------------------------------------------------------------------
__device__ __forceinline__ uint32_t s2u(const void* p) {
    return (uint32_t)__cvta_generic_to_shared(p);
}
__device__ __forceinline__ void cpa(uint32_t d, const void* s) {
    asm volatile("cp.async.cg.shared.global [%0], [%1], 16;" :: "r"(d), "l"(s));
}
__device__ __forceinline__ void cpcommit() {
    asm volatile("cp.async.commit_group;");
}
template <int N> __device__ __forceinline__ void cpwait() {
    asm volatile("cp.async.wait_group %0;" :: "n"(N));
}

__device__ __forceinline__ void ldm4(uint32_t r[4], uint32_t a) {
    asm volatile("ldmatrix.sync.aligned.m8n8.x4.shared.b16 {%0,%1,%2,%3}, [%4];"
                 : "=r"(r[0]), "=r"(r[1]), "=r"(r[2]), "=r"(r[3]) : "r"(a));
}
__device__ __forceinline__ void ldm4t(uint32_t r[4], uint32_t a) {
    asm volatile("ldmatrix.sync.aligned.m8n8.x4.trans.shared.b16 {%0,%1,%2,%3}, [%4];"
                 : "=r"(r[0]), "=r"(r[1]), "=r"(r[2]), "=r"(r[3]) : "r"(a));
}

__device__ __forceinline__ void mma_f16(float c[4], const uint32_t a[4],
                                        uint32_t b0, uint32_t b1) {
    asm volatile(
        "mma.sync.aligned.m16n8k16.row.col.f32.f16.f16.f32 "
        "{%0,%1,%2,%3}, {%4,%5,%6,%7}, {%8,%9}, {%0,%1,%2,%3};\n"
        : "+f"(c[0]), "+f"(c[1]), "+f"(c[2]), "+f"(c[3])
        : "r"(a[0]), "r"(a[1]), "r"(a[2]), "r"(a[3]), "r"(b0), "r"(b1));
}

__device__ __forceinline__ uint32_t packh2(float lo, float hi) {
    __half2 h = __floats2half2_rn(lo, hi);
    return *reinterpret_cast<uint32_t*>(&h);
}

// ---------------------------------------------------------------------------
// Convert inputs + weights to fp16. grid (1536, 1, 7); z<3: inputs, z>=3: weights.
// ---------------------------------------------------------------------------
__global__ __launch_bounds__(256) void conv_all(const float* __restrict__ q,
                                                const float* __restrict__ k,
                                                const float* __restrict__ v,
                                                const float* __restrict__ wq,
                                                const float* __restrict__ wk,
                                                const float* __restrict__ wv,
                                                const float* __restrict__ wo,
                                                __half* __restrict__ X,
                                                __half* __restrict__ W)
{
    const int z = blockIdx.z;
    const float* src;
    __half* dst;
    int nblk;
    if (z < 3) {
        src = (z == 0) ? q : (z == 1) ? k : v;
        dst = X + (size_t)z * CL * CE;
        nblk = CL * CE / 2048;
    } else {
        src = (z == 3) ? wq : (z == 4) ? wk : (z == 5) ? wv : wo;
        dst = W + (size_t)(z - 3) * CE * CE;
        nblk = CE * CE / 2048;
    }
    if (blockIdx.x >= nblk) return;
    size_t i = ((size_t)blockIdx.x * 256 + threadIdx.x) * 8;
    float4 v0 = *(const float4*)&src[i];
    float4 v1 = *(const float4*)&src[i + 4];
    uint32_t h[4];
    h[0] = packh2(v0.x, v0.y);
    h[1] = packh2(v0.z, v0.w);
    h[2] = packh2(v1.x, v1.y);
    h[3] = packh2(v1.z, v1.w);
    *(uint4*)&dst[i] = *(uint4*)h;
}

// ---------------------------------------------------------------------------
// Pack mask to bits, vectorized: bit i of word w = mask[w*32+i] != 0
// ---------------------------------------------------------------------------
__global__ __launch_bounds__(256) void pack_mask(const int* __restrict__ m,
                                                 uint32_t* __restrict__ mb) {
    __shared__ uint32_t nib[256];
    int t = threadIdx.x;
    size_t base = (size_t)blockIdx.x * 1024 + (size_t)t * 4;
    int4 v = *(const int4*)&m[base];
    nib[t] = (v.x ? 1u : 0u) | (v.y ? 2u : 0u) | (v.z ? 4u : 0u) | (v.w ? 8u : 0u);
    __syncthreads();
    if (t < 32) {
        uint32_t w = 0;
#pragma unroll
        for (int j = 0; j < 8; j++) w |= nib[t * 8 + j] << (4 * j);
        mb[(size_t)blockIdx.x * 32 + t] = w;
    }
}

// ---------------------------------------------------------------------------
// fp16 GEMM core, cp.async double-buffered + ldmatrix. 128 thr (4 warps),
// CTA tile 128x64, warp 32x64, k-step 64. A[M,768] @ W[768,64-slice].
// ---------------------------------------------------------------------------
__device__ __forceinline__ void gemm_body(const __half* __restrict__ A,
                                          const __half* __restrict__ W,
                                          const float* __restrict__ bias,
                                          float* __restrict__ Cf,
                                          __half* __restrict__ Ch,
                                          int m0, int n0, char* sgc)
{
    __half* smA = (__half*)sgc;             // 2 x 128 x HSTR
    __half* smW = smA + 2 * 128 * HSTR;     // 2 x 64 x HSTR

    const int tid = threadIdx.x;
    const int wid = tid >> 5;
    const int ln  = tid & 31;
    const int gid = ln >> 2;
    const int tig = ln & 3;
    const int qb  = wid * 32;

    // lane-constant ldmatrix byte offsets (within a buffer)
    const uint32_t aoff0 = (uint32_t)(((qb + (ln & 15)) * HSTR + (ln >> 4) * 8) << 1);
    const uint32_t aoff1 = aoff0 + (16 * HSTR << 1);
    const uint32_t woff  = (uint32_t)(((((ln & 7) + ((ln >> 3) & 1) * 8) * HSTR) + (ln >> 4) * 8) << 1);
    const uint32_t smAu = s2u(smA);
    const uint32_t smWu = s2u(smW);

    auto issue = [&](int k0, int b) {
        __half* dA = smA + b * 128 * HSTR;
        __half* dW = smW + b * 64 * HSTR;
#pragma unroll
        for (int i = 0; i < 8; i++) {
            int lin = tid + i * 128;
            int row = lin >> 3, ch = (lin & 7) * 8;
            cpa(s2u(&dA[row * HSTR + ch]), &A[(size_t)(m0 + row) * CE + k0 + ch]);
        }
#pragma unroll
        for (int i = 0; i < 4; i++) {
            int lin = tid + i * 128;
            int kr = lin >> 3, ch = (lin & 7) * 8;
            cpa(s2u(&dW[kr * HSTR + ch]), &W[(size_t)(k0 + kr) * CE + n0 + ch]);
        }
        cpcommit();
    };

    float c[2][8][4];
#pragma unroll
    for (int m = 0; m < 2; m++)
#pragma unroll
        for (int nf = 0; nf < 8; nf++)
#pragma unroll
            for (int j = 0; j < 4; j++) c[m][nf][j] = 0.f;

    const int NS = CE / 64;  // 12
    issue(0, 0);
    issue(64, 1);

    for (int ks = 0; ks < NS; ks++) {
        const int buf = ks & 1;
        if (ks < NS - 1) cpwait<1>(); else cpwait<0>();
        __syncthreads();

        const uint32_t aBuf = smAu + (uint32_t)(buf * 128 * HSTR * 2);
        const uint32_t wBuf = smWu + (uint32_t)(buf * 64 * HSTR * 2);

#pragma unroll
        for (int g = 0; g < 4; g++) {
            uint32_t a0[4], a1[4];
            ldm4(a0, aBuf + aoff0 + g * 32);
            ldm4(a1, aBuf + aoff1 + g * 32);
#pragma unroll
            for (int np = 0; np < 4; np++) {
                uint32_t b[4];
                ldm4t(b, wBuf + woff + (uint32_t)(g * (16 * HSTR * 2) + np * 32));
                mma_f16(c[0][2 * np],     a0, b[0], b[1]);
                mma_f16(c[0][2 * np + 1], a0, b[2], b[3]);
                mma_f16(c[1][2 * np],     a1, b[0], b[1]);
                mma_f16(c[1][2 * np + 1], a1, b[2], b[3]);
            }
        }
        __syncthreads();
        if (ks + 2 < NS) issue((ks + 2) * 64, buf);
    }

#pragma unroll
    for (int m = 0; m < 2; m++) {
        int r0 = m0 + qb + m * 16 + gid;
        int r1 = r0 + 8;
#pragma unroll
        for (int nf = 0; nf < 8; nf++) {
            int n = n0 + nf * 8 + 2 * tig;
            if (Ch) {
                *(__half2*)&Ch[(size_t)r0 * CE + n] =
                    __floats2half2_rn(c[m][nf][0], c[m][nf][1]);
                *(__half2*)&Ch[(size_t)r1 * CE + n] =
                    __floats2half2_rn(c[m][nf][2], c[m][nf][3]);
            } else {
                float b0v = bias[n], b1v = bias[n + 1];
                *(float2*)&Cf[(size_t)r0 * CE + n] =
                    make_float2(c[m][nf][0] + b0v, c[m][nf][1] + b1v);
                *(float2*)&Cf[(size_t)r1 * CE + n] =
                    make_float2(c[m][nf][2] + b0v, c[m][nf][3] + b1v);
            }
        }
    }
}

__global__ __launch_bounds__(128) void gemm_proj(const __half* __restrict__ X,
                                                 const __half* __restrict__ W,
                                                 __half* __restrict__ Qp,
                                                 __half* __restrict__ Kp,
                                                 __half* __restrict__ Vp)
{
    extern __shared__ char sgc[];
    const int z = blockIdx.z;
    const __half* A = X + (size_t)z * CL * CE;
    const __half* Wz = W + (size_t)z * CE * CE;
    __half* C = (z == 0) ? Qp : (z == 1) ? Kp : Vp;
    gemm_body(A, Wz, nullptr, nullptr, C, blockIdx.y * 128, blockIdx.x * 64, sgc);
}

__global__ __launch_bounds__(128) void gemm_out(const __half* __restrict__ A,
                                                const __half* __restrict__ W,
                                                const float* __restrict__ bias,
                                                float* __restrict__ C)
{
    extern __shared__ char sgc[];
    gemm_body(A, W, bias, C, nullptr, blockIdx.y * 128, blockIdx.x * 64, sgc);
}

// ---------------------------------------------------------------------------
// Flash attention fp16: cp.async double-buffered K/V, ldmatrix fragments,
// zero-copy P (S C-frag == PV A-frag). Block = (128 q, head), 8 warps x 16 rows.
// ---------------------------------------------------------------------------
__global__ __launch_bounds__(256) void flash_h(const __half* __restrict__ Qg,
                                               const __half* __restrict__ Kg,
                                               const __half* __restrict__ Vg,
                                               const uint32_t* __restrict__ MBg,
                                               __half* __restrict__ Og)
{
    extern __shared__ char smc[];
    __half* Qs = (__half*)smc;              // 128 x HSTR
    __half* Ks = Qs + 128 * HSTR;           // 2 x 64 x HSTR
    __half* Vs = Ks + 2 * 64 * HSTR;        // 2 x 64 x HSTR

    const uint2* MB2 = (const uint2*)MBg;

    const int h  = blockIdx.y;
    const int q0 = blockIdx.x * 128;
    const int tid = threadIdx.x;
    const int wid = tid >> 5;
    const int ln  = tid & 31;
    const int gid = ln >> 2;
    const int tig = ln & 3;
    const int qb = wid * 16;

    // lane-constant ldmatrix byte offsets
    const uint32_t qBase = s2u(Qs) + (uint32_t)(((qb + (ln & 15)) * HSTR + (ln >> 4) * 8) << 1);
    const uint32_t kOff  = (uint32_t)(((((ln & 7) + ((ln >> 4) & 1) * 8) * HSTR) + ((ln >> 3) & 1) * 8) << 1);
    const uint32_t vOff  = (uint32_t)(((((ln & 7) + ((ln >> 3) & 1) * 8) * HSTR) + (ln >> 4) * 8) << 1);
    const uint32_t KsU = s2u(Ks);
    const uint32_t VsU = s2u(Vs);

    auto issueKV = [&](int k0, int b) {
        __half* dK = Ks + b * 64 * HSTR;
        __half* dV = Vs + b * 64 * HSTR;
#pragma unroll
        for (int i = 0; i < 2; i++) {
            int lin = tid + i * 256;
            int row = lin >> 3, ch = (lin & 7) * 8;
            cpa(s2u(&dK[row * HSTR + ch]), &Kg[(size_t)(k0 + row) * CE + h * CD + ch]);
            cpa(s2u(&dV[row * HSTR + ch]), &Vg[(size_t)(k0 + row) * CE + h * CD + ch]);
        }
        cpcommit();
    };

    // prologue: Q (folded into group 0) + KV tile0, KV tile1
#pragma unroll
    for (int i = 0; i < 4; i++) {
        int lin = tid + i * 256;
        int row = lin >> 3, ch = (lin & 7) * 8;
        cpa(s2u(&Qs[row * HSTR + ch]), &Qg[(size_t)(q0 + row) * CE + h * CD + ch]);
    }
    issueKV(0, 0);
    issueKV(64, 1);

    float m_i[2] = {-1e30f, -1e30f};
    float l_i[2] = {0.f, 0.f};
    float o[8][4];
#pragma unroll
    for (int nf = 0; nf < 8; nf++)
#pragma unroll
        for (int j = 0; j < 4; j++) o[nf][j] = 0.f;

    const int mrow = q0 + qb + gid;
    const int NT = CS / 64;  // 64

    for (int t = 0; t < NT; t++) {
        const int buf = t & 1;

        uint2 mw0 = MB2[(size_t)mrow * 64 + t];
        uint2 mw1 = MB2[(size_t)(mrow + 8) * 64 + t];

        if (t < NT - 1) cpwait<1>(); else cpwait<0>();
        __syncthreads();

        const uint32_t kBuf = KsU + (uint32_t)(buf * 64 * HSTR * 2);
        const uint32_t vBuf = VsU + (uint32_t)(buf * 64 * HSTR * 2);

        // S = Q @ K^T  (warp: 16 x 64)
        float s[8][4];
#pragma unroll
        for (int nf = 0; nf < 8; nf++)
#pragma unroll
            for (int j = 0; j < 4; j++) s[nf][j] = 0.f;

#pragma unroll
        for (int g = 0; g < 4; g++) {
            uint32_t a[4];
            ldm4(a, qBase + g * 32);
#pragma unroll
            for (int np = 0; np < 4; np++) {
                uint32_t b[4];
                ldm4(b, kBuf + kOff + (uint32_t)(np * (16 * HSTR * 2) + g * 32));
                mma_f16(s[2 * np],     a, b[0], b[1]);
                mma_f16(s[2 * np + 1], a, b[2], b[3]);
            }
        }

        // scale + online softmax + mask
        {
#pragma unroll
            for (int nf = 0; nf < 8; nf++)
#pragma unroll
                for (int j = 0; j < 4; j++) s[nf][j] *= INV_SCALE;

            float mx0 = -1e30f, mx1 = -1e30f;
#pragma unroll
            for (int nf = 0; nf < 8; nf++) {
                mx0 = fmaxf(mx0, fmaxf(s[nf][0], s[nf][1]));
                mx1 = fmaxf(mx1, fmaxf(s[nf][2], s[nf][3]));
            }
#pragma unroll
            for (int off = 1; off <= 2; off <<= 1) {
                mx0 = fmaxf(mx0, __shfl_xor_sync(0xffffffffu, mx0, off));
                mx1 = fmaxf(mx1, __shfl_xor_sync(0xffffffffu, mx1, off));
            }
            float mn0 = fmaxf(m_i[0], mx0);
            float mn1 = fmaxf(m_i[1], mx1);
            float cr0 = __expf(m_i[0] - mn0);
            float cr1 = __expf(m_i[1] - mn1);

            float sum0 = 0.f, sum1 = 0.f;
#pragma unroll
            for (int nf = 0; nf < 8; nf++) {
                uint32_t w0 = (nf < 4) ? mw0.x : mw0.y;
                uint32_t w1 = (nf < 4) ? mw1.x : mw1.y;
                int sh = ((nf & 3) << 3) + 2 * tig;
                float p0 = __expf(s[nf][0] - mn0);
                float p1 = __expf(s[nf][1] - mn0);
                float p2 = __expf(s[nf][2] - mn1);
                float p3 = __expf(s[nf][3] - mn1);
                p0 = ((w0 >> sh) & 1) ? p0 : 0.f;
                p1 = ((w0 >> (sh + 1)) & 1) ? p1 : 0.f;
                p2 = ((w1 >> sh) & 1) ? p2 : 0.f;
                p3 = ((w1 >> (sh + 1)) & 1) ? p3 : 0.f;
                s[nf][0] = p0; s[nf][1] = p1;
                s[nf][2] = p2; s[nf][3] = p3;
                sum0 += p0 + p1;
                sum1 += p2 + p3;
            }
#pragma unroll
            for (int off = 1; off <= 2; off <<= 1) {
                sum0 += __shfl_xor_sync(0xffffffffu, sum0, off);
                sum1 += __shfl_xor_sync(0xffffffffu, sum1, off);
            }
            l_i[0] = l_i[0] * cr0 + sum0;
            l_i[1] = l_i[1] * cr1 + sum1;
            m_i[0] = mn0;
            m_i[1] = mn1;
#pragma unroll
            for (int nf = 0; nf < 8; nf++) {
                o[nf][0] *= cr0; o[nf][1] *= cr0;
                o[nf][2] *= cr1; o[nf][3] *= cr1;
            }
        }

        // O += P @ V : C-frag -> A-frag is a pure pack (no shuffles)
#pragma unroll
        for (int g = 0; g < 4; g++) {
            uint32_t pa[4];
            pa[0] = packh2(s[2 * g][0],     s[2 * g][1]);
            pa[1] = packh2(s[2 * g][2],     s[2 * g][3]);
            pa[2] = packh2(s[2 * g + 1][0], s[2 * g + 1][1]);
            pa[3] = packh2(s[2 * g + 1][2], s[2 * g + 1][3]);
#pragma unroll
            for (int np = 0; np < 4; np++) {
                uint32_t b[4];
                ldm4t(b, vBuf + vOff + (uint32_t)(g * (16 * HSTR * 2) + np * 32));
                mma_f16(o[2 * np],     pa, b[0], b[1]);
                mma_f16(o[2 * np + 1], pa, b[2], b[3]);
            }
        }

        __syncthreads();
        if (t + 2 < NT) issueKV((t + 2) * 64, buf);
    }

    // epilogue (fp16 O for the output GEMM)
    float inv0 = (l_i[0] > 0.f) ? (1.f / l_i[0]) : 0.f;
    float inv1 = (l_i[1] > 0.f) ? (1.f / l_i[1]) : 0.f;
    const int r0 = q0 + qb + gid;
#pragma unroll
    for (int nf = 0; nf < 8; nf++) {
        int cc = h * CD + nf * 8 + 2 * tig;
        *(__half2*)&Og[(size_t)r0 * CE + cc] =
            __floats2half2_rn(o[nf][0] * inv0, o[nf][1] * inv0);
        *(__half2*)&Og[(size_t)(r0 + 8) * CE + cc] =
            __floats2half2_rn(o[nf][2] * inv1, o[nf][3] * inv1);
    }
}

// ---------------------------------------------------------------------------

extern "C" void kernel_launch(void* const* d_in, const int* in_sizes, int n_in,
                              void* d_out, int out_size)
{
    const float* query = (const float*)d_in[0];
    const float* key   = (const float*)d_in[1];
    const float* value = (const float*)d_in[2];
    const int*   mask  = (const int*)d_in[3];
    const float* Wq    = (const float*)d_in[4];
    const float* Wk    = (const float*)d_in[5];
    const float* Wv    = (const float*)d_in[6];
    const float* Wo    = (const float*)d_in[7];
    const float* bo    = (const float*)d_in[8];
    float* out = (float*)d_out;

    __half *Qp, *Kp, *Vp, *Op, *Xp, *Wp;
    uint32_t* MBp;
    cudaGetSymbolAddress((void**)&Qp, g_Q);
    cudaGetSymbolAddress((void**)&Kp, g_K);
    cudaGetSymbolAddress((void**)&Vp, g_V);
    cudaGetSymbolAddress((void**)&Op, g_O);
    cudaGetSymbolAddress((void**)&Xp, g_X);
    cudaGetSymbolAddress((void**)&Wp, g_W);
    cudaGetSymbolAddress((void**)&MBp, g_MB);

    const int gemm_smem  = (2 * 128 + 2 * 64) * HSTR * 2;        // 55296
    const int flash_smem = (128 + 2 * 64 + 2 * 64) * HSTR * 2;   // 55296

    cudaFuncSetAttribute(gemm_proj, cudaFuncAttributeMaxDynamicSharedMemorySize, gemm_smem);
    cudaFuncSetAttribute(gemm_out, cudaFuncAttributeMaxDynamicSharedMemorySize, gemm_smem);
    cudaFuncSetAttribute(flash_h, cudaFuncAttributeMaxDynamicSharedMemorySize, flash_smem);

    conv_all<<<dim3(CL * CE / 2048, 1, 7), 256>>>(query, key, value,
                                                  Wq, Wk, Wv, Wo, Xp, Wp);

    pack_mask<<<(CL * CS) / 1024, 256>>>(mask, MBp);

    gemm_proj<<<dim3(CE / 64, CL / 128, 3), 128, gemm_smem>>>(Xp, Wp, Qp, Kp, Vp);

    flash_h<<<dim3(CL / 128, CH), 256, flash_smem>>>(Qp, Kp, Vp, MBp, Op);

    gemm_out<<<dim3(CE / 64, CL / 128), 128, gemm_smem>>>(
        Op, Wp + (size_t)3 * CE * CE, bo, out);
}

// round 7
// speedup vs baseline: 1.8376x; 1.0183x over previous
#include <cuda_runtime.h>
#include <cuda_fp16.h>
#include <cstdint>

#define CL 4096
#define CS 4096
#define CE 768
#define CH 12
#define CD 64
#define HSTR 72   // half-row stride: 144B -> 16B-aligned rows, bank-quad pattern 0,4,..28

static __device__ __host__ constexpr float INV_SCALE = 0.036084391824351614f; // 1/sqrt(768)

// Scratch (no cudaMalloc allowed)
__device__ __half g_Q[CL * CE];
__device__ __half g_K[CS * CE];
__device__ __half g_V[CS * CE];
__device__ __half g_O[CL * CE];
__device__ __half g_X[(size_t)CL * CE * 3];  // fp16 inputs q,k,v
__device__ __half g_W[(size_t)CE * CE * 4];  // fp16 weights Wq,Wk,Wv,Wo
__device__ uint32_t g_MB[(size_t)CL * CS / 32];

// ---------------------------------------------------------------------------
__device__ __forceinline__ uint32_t s2u(const void* p) {
    return (uint32_t)__cvta_generic_to_shared(p);
}
__device__ __forceinline__ void cpa(uint32_t d, const void* s) {
    asm volatile("cp.async.cg.shared.global [%0], [%1], 16;" :: "r"(d), "l"(s));
}
__device__ __forceinline__ void cpcommit() {
    asm volatile("cp.async.commit_group;");
}
template <int N> __device__ __forceinline__ void cpwait() {
    asm volatile("cp.async.wait_group %0;" :: "n"(N));
}

__device__ __forceinline__ void ldm4(uint32_t r[4], uint32_t a) {
    asm volatile("ldmatrix.sync.aligned.m8n8.x4.shared.b16 {%0,%1,%2,%3}, [%4];"
                 : "=r"(r[0]), "=r"(r[1]), "=r"(r[2]), "=r"(r[3]) : "r"(a));
}
__device__ __forceinline__ void ldm4t(uint32_t r[4], uint32_t a) {
    asm volatile("ldmatrix.sync.aligned.m8n8.x4.trans.shared.b16 {%0,%1,%2,%3}, [%4];"
                 : "=r"(r[0]), "=r"(r[1]), "=r"(r[2]), "=r"(r[3]) : "r"(a));
}

__device__ __forceinline__ void mma_f16(float c[4], const uint32_t a[4],
                                        uint32_t b0, uint32_t b1) {
    asm volatile(
        "mma.sync.aligned.m16n8k16.row.col.f32.f16.f16.f32 "
        "{%0,%1,%2,%3}, {%4,%5,%6,%7}, {%8,%9}, {%0,%1,%2,%3};\n"
        : "+f"(c[0]), "+f"(c[1]), "+f"(c[2]), "+f"(c[3])
        : "r"(a[0]), "r"(a[1]), "r"(a[2]), "r"(a[3]), "r"(b0), "r"(b1));
}

__device__ __forceinline__ uint32_t packh2(float lo, float hi) {
    __half2 h = __floats2half2_rn(lo, hi);
    return *reinterpret_cast<uint32_t*>(&h);
}

__device__ __forceinline__ float ex2(float x) {
    float r;
    asm("ex2.approx.f32 %0, %1;" : "=f"(r) : "f"(x));
    return r;
}

// ---------------------------------------------------------------------------
// Convert inputs + weights to fp16. grid (1536, 1, 7); z<3: inputs, z>=3: weights.
// ---------------------------------------------------------------------------
__global__ __launch_bounds__(256) void conv_all(const float* __restrict__ q,
                                                const float* __restrict__ k,
                                                const float* __restrict__ v,
                                                const float* __restrict__ wq,
                                                const float* __restrict__ wk,
                                                const float* __restrict__ wv,
                                                const float* __restrict__ wo,
                                                __half* __restrict__ X,
                                                __half* __restrict__ W)
{
    const int z = blockIdx.z;
    const float* src;
    __half* dst;
    int nblk;
    if (z < 3) {
        src = (z == 0) ? q : (z == 1) ? k : v;
        dst = X + (size_t)z * CL * CE;
        nblk = CL * CE / 2048;
    } else {
        src = (z == 3) ? wq : (z == 4) ? wk : (z == 5) ? wv : wo;
        dst = W + (size_t)(z - 3) * CE * CE;
        nblk = CE * CE / 2048;
    }
    if (blockIdx.x >= nblk) return;
    size_t i = ((size_t)blockIdx.x * 256 + threadIdx.x) * 8;
    float4 v0 = *(const float4*)&src[i];
    float4 v1 = *(const float4*)&src[i + 4];
    uint32_t h[4];
    h[0] = packh2(v0.x, v0.y);
    h[1] = packh2(v0.z, v0.w);
    h[2] = packh2(v1.x, v1.y);
    h[3] = packh2(v1.z, v1.w);
    *(uint4*)&dst[i] = *(uint4*)h;
}

// ---------------------------------------------------------------------------
// Pack mask to bits, vectorized: bit i of word w = mask[w*32+i] != 0
// ---------------------------------------------------------------------------
__global__ __launch_bounds__(256) void pack_mask(const int* __restrict__ m,
                                                 uint32_t* __restrict__ mb) {
    __shared__ uint32_t nib[256];
    int t = threadIdx.x;
    size_t base = (size_t)blockIdx.x * 1024 + (size_t)t * 4;
    int4 v = *(const int4*)&m[base];
    nib[t] = (v.x ? 1u : 0u) | (v.y ? 2u : 0u) | (v.z ? 4u : 0u) | (v.w ? 8u : 0u);
    __syncthreads();
    if (t < 32) {
        uint32_t w = 0;
#pragma unroll
        for (int j = 0; j < 8; j++) w |= nib[t * 8 + j] << (4 * j);
        mb[(size_t)blockIdx.x * 32 + t] = w;
    }
}

// ---------------------------------------------------------------------------
// fp16 GEMM core, cp.async double-buffered + ldmatrix. 128 thr (4 warps),
// CTA tile 128x64, warp 32x64, k-step 64. A[M,768] @ W[768,64-slice].
// ---------------------------------------------------------------------------
__device__ __forceinline__ void gemm_body(const __half* __restrict__ A,
                                          const __half* __restrict__ W,
                                          const float* __restrict__ bias,
                                          float* __restrict__ Cf,
                                          __half* __restrict__ Ch,
                                          int m0, int n0, char* sgc)
{
    __half* smA = (__half*)sgc;             // 2 x 128 x HSTR
    __half* smW = smA + 2 * 128 * HSTR;     // 2 x 64 x HSTR

    const int tid = threadIdx.x;
    const int wid = tid >> 5;
    const int ln  = tid & 31;
    const int gid = ln >> 2;
    const int tig = ln & 3;
    const int qb  = wid * 32;

    // lane-constant ldmatrix byte offsets (within a buffer)
    const uint32_t aoff0 = (uint32_t)(((qb + (ln & 15)) * HSTR + (ln >> 4) * 8) << 1);
    const uint32_t aoff1 = aoff0 + (16 * HSTR << 1);
    const uint32_t woff  = (uint32_t)(((((ln & 7) + ((ln >> 3) & 1) * 8) * HSTR) + (ln >> 4) * 8) << 1);
    const uint32_t smAu = s2u(smA);
    const uint32_t smWu = s2u(smW);

    auto issue = [&](int k0, int b) {
        __half* dA = smA + b * 128 * HSTR;
        __half* dW = smW + b * 64 * HSTR;
#pragma unroll
        for (int i = 0; i < 8; i++) {
            int lin = tid + i * 128;
            int row = lin >> 3, ch = (lin & 7) * 8;
            cpa(s2u(&dA[row * HSTR + ch]), &A[(size_t)(m0 + row) * CE + k0 + ch]);
        }
#pragma unroll
        for (int i = 0; i < 4; i++) {
            int lin = tid + i * 128;
            int kr = lin >> 3, ch = (lin & 7) * 8;
            cpa(s2u(&dW[kr * HSTR + ch]), &W[(size_t)(k0 + kr) * CE + n0 + ch]);
        }
        cpcommit();
    };

    float c[2][8][4];
#pragma unroll
    for (int m = 0; m < 2; m++)
#pragma unroll
        for (int nf = 0; nf < 8; nf++)
#pragma unroll
            for (int j = 0; j < 4; j++) c[m][nf][j] = 0.f;

    const int NS = CE / 64;  // 12
    issue(0, 0);
    issue(64, 1);

    for (int ks = 0; ks < NS; ks++) {
        const int buf = ks & 1;
        if (ks < NS - 1) cpwait<1>(); else cpwait<0>();
        __syncthreads();

        const uint32_t aBuf = smAu + (uint32_t)(buf * 128 * HSTR * 2);
        const uint32_t wBuf = smWu + (uint32_t)(buf * 64 * HSTR * 2);

#pragma unroll
        for (int g = 0; g < 4; g++) {
            uint32_t a0[4], a1[4];
            ldm4(a0, aBuf + aoff0 + g * 32);
            ldm4(a1, aBuf + aoff1 + g * 32);
#pragma unroll
            for (int np = 0; np < 4; np++) {
                uint32_t b[4];
                ldm4t(b, wBuf + woff + (uint32_t)(g * (16 * HSTR * 2) + np * 32));
                mma_f16(c[0][2 * np],     a0, b[0], b[1]);
                mma_f16(c[0][2 * np + 1], a0, b[2], b[3]);
                mma_f16(c[1][2 * np],     a1, b[0], b[1]);
                mma_f16(c[1][2 * np + 1], a1, b[2], b[3]);
            }
        }
        __syncthreads();
        if (ks + 2 < NS) issue((ks + 2) * 64, buf);
    }

#pragma unroll
    for (int m = 0; m < 2; m++) {
        int r0 = m0 + qb + m * 16 + gid;
        int r1 = r0 + 8;
#pragma unroll
        for (int nf = 0; nf < 8; nf++) {
            int n = n0 + nf * 8 + 2 * tig;
            if (Ch) {
                *(__half2*)&Ch[(size_t)r0 * CE + n] =
                    __floats2half2_rn(c[m][nf][0], c[m][nf][1]);
                *(__half2*)&Ch[(size_t)r1 * CE + n] =
                    __floats2half2_rn(c[m][nf][2], c[m][nf][3]);
            } else {
                float b0v = bias[n], b1v = bias[n + 1];
                *(float2*)&Cf[(size_t)r0 * CE + n] =
                    make_float2(c[m][nf][0] + b0v, c[m][nf][1] + b1v);
                *(float2*)&Cf[(size_t)r1 * CE + n] =
                    make_float2(c[m][nf][2] + b0v, c[m][nf][3] + b1v);
            }
        }
    }
}

__global__ __launch_bounds__(128) void gemm_proj(const __half* __restrict__ X,
                                                 const __half* __restrict__ W,
                                                 __half* __restrict__ Qp,
                                                 __half* __restrict__ Kp,
                                                 __half* __restrict__ Vp)
{
    extern __shared__ char sgc[];
    const int z = blockIdx.z;
    const __half* A = X + (size_t)z * CL * CE;
    const __half* Wz = W + (size_t)z * CE * CE;
    __half* C = (z == 0) ? Qp : (z == 1) ? Kp : Vp;
    gemm_body(A, Wz, nullptr, nullptr, C, blockIdx.y * 128, blockIdx.x * 64, sgc);
}

__global__ __launch_bounds__(128) void gemm_out(const __half* __restrict__ A,
                                                const __half* __restrict__ W,
                                                const float* __restrict__ bias,
                                                float* __restrict__ C)
{
    extern __shared__ char sgc[];
    gemm_body(A, W, bias, C, nullptr, blockIdx.y * 128, blockIdx.x * 64, sgc);
}

// ---------------------------------------------------------------------------
// Flash attention fp16: cp.async double-buffered K/V, ldmatrix fragments,
// zero-copy P, scalar-lean softmax (folded exp2, mask fast path, lazy rescale).
// Block = (128 q, head), 8 warps x 16 rows.
// ---------------------------------------------------------------------------
__global__ __launch_bounds__(256) void flash_h(const __half* __restrict__ Qg,
                                               const __half* __restrict__ Kg,
                                               const __half* __restrict__ Vg,
                                               const uint32_t* __restrict__ MBg,
                                               __half* __restrict__ Og)
{
    extern __shared__ char smc[];
    __half* Qs = (__half*)smc;              // 128 x HSTR
    __half* Ks = Qs + 128 * HSTR;           // 2 x 64 x HSTR
    __half* Vs = Ks + 2 * 64 * HSTR;        // 2 x 64 x HSTR

    const uint2* MB2 = (const uint2*)MBg;
    const float CEXP = 0.05205889686f;      // INV_SCALE * log2(e)

    const int h  = blockIdx.y;
    const int q0 = blockIdx.x * 128;
    const int tid = threadIdx.x;
    const int wid = tid >> 5;
    const int ln  = tid & 31;
    const int gid = ln >> 2;
    const int tig = ln & 3;
    const int qb = wid * 16;

    // lane-constant ldmatrix byte offsets
    const uint32_t qBase = s2u(Qs) + (uint32_t)(((qb + (ln & 15)) * HSTR + (ln >> 4) * 8) << 1);
    const uint32_t kOff  = (uint32_t)(((((ln & 7) + ((ln >> 4) & 1) * 8) * HSTR) + ((ln >> 3) & 1) * 8) << 1);
    const uint32_t vOff  = (uint32_t)(((((ln & 7) + ((ln >> 3) & 1) * 8) * HSTR) + (ln >> 4) * 8) << 1);
    const uint32_t KsU = s2u(Ks);
    const uint32_t VsU = s2u(Vs);

    auto issueKV = [&](int k0, int b) {
        __half* dK = Ks + b * 64 * HSTR;
        __half* dV = Vs + b * 64 * HSTR;
#pragma unroll
        for (int i = 0; i < 2; i++) {
            int lin = tid + i * 256;
            int row = lin >> 3, ch = (lin & 7) * 8;
            cpa(s2u(&dK[row * HSTR + ch]), &Kg[(size_t)(k0 + row) * CE + h * CD + ch]);
            cpa(s2u(&dV[row * HSTR + ch]), &Vg[(size_t)(k0 + row) * CE + h * CD + ch]);
        }
        cpcommit();
    };

    // prologue: Q (folded into group 0) + KV tile0, KV tile1
#pragma unroll
    for (int i = 0; i < 4; i++) {
        int lin = tid + i * 256;
        int row = lin >> 3, ch = (lin & 7) * 8;
        cpa(s2u(&Qs[row * HSTR + ch]), &Qg[(size_t)(q0 + row) * CE + h * CD + ch]);
    }
    issueKV(0, 0);
    issueKV(64, 1);

    float m_i[2] = {-1e30f, -1e30f};   // raw (unscaled) units
    float l_i[2] = {0.f, 0.f};
    float o[8][4];
#pragma unroll
    for (int nf = 0; nf < 8; nf++)
#pragma unroll
        for (int j = 0; j < 4; j++) o[nf][j] = 0.f;

    const int mrow = q0 + qb + gid;
    const int NT = CS / 64;  // 64

    for (int t = 0; t < NT; t++) {
        const int buf = t & 1;

        uint2 mw0 = MB2[(size_t)mrow * 64 + t];
        uint2 mw1 = MB2[(size_t)(mrow + 8) * 64 + t];

        if (t < NT - 1) cpwait<1>(); else cpwait<0>();
        __syncthreads();

        const uint32_t kBuf = KsU + (uint32_t)(buf * 64 * HSTR * 2);
        const uint32_t vBuf = VsU + (uint32_t)(buf * 64 * HSTR * 2);

        // S = Q @ K^T  (warp: 16 x 64), raw units
        float s[8][4];
#pragma unroll
        for (int nf = 0; nf < 8; nf++)
#pragma unroll
            for (int j = 0; j < 4; j++) s[nf][j] = 0.f;

#pragma unroll
        for (int g = 0; g < 4; g++) {
            uint32_t a[4];
            ldm4(a, qBase + g * 32);
#pragma unroll
            for (int np = 0; np < 4; np++) {
                uint32_t b[4];
                ldm4(b, kBuf + kOff + (uint32_t)(np * (16 * HSTR * 2) + g * 32));
                mma_f16(s[2 * np],     a, b[0], b[1]);
                mma_f16(s[2 * np + 1], a, b[2], b[3]);
            }
        }

        // online softmax: p = 2^((s - mn)*CEXP), mask fast-path, lazy rescale
        {
            float mx0 = -1e30f, mx1 = -1e30f;
#pragma unroll
            for (int nf = 0; nf < 8; nf++) {
                mx0 = fmaxf(mx0, fmaxf(s[nf][0], s[nf][1]));
                mx1 = fmaxf(mx1, fmaxf(s[nf][2], s[nf][3]));
            }
#pragma unroll
            for (int off = 1; off <= 2; off <<= 1) {
                mx0 = fmaxf(mx0, __shfl_xor_sync(0xffffffffu, mx0, off));
                mx1 = fmaxf(mx1, __shfl_xor_sync(0xffffffffu, mx1, off));
            }
            float mn0 = fmaxf(m_i[0], mx0);
            float mn1 = fmaxf(m_i[1], mx1);
            float cr0 = ex2((m_i[0] - mn0) * CEXP);
            float cr1 = ex2((m_i[1] - mn1) * CEXP);
            float mn0C = mn0 * CEXP;
            float mn1C = mn1 * CEXP;

#pragma unroll
            for (int nf = 0; nf < 8; nf++) {
                s[nf][0] = ex2(fmaf(s[nf][0], CEXP, -mn0C));
                s[nf][1] = ex2(fmaf(s[nf][1], CEXP, -mn0C));
                s[nf][2] = ex2(fmaf(s[nf][2], CEXP, -mn1C));
                s[nf][3] = ex2(fmaf(s[nf][3], CEXP, -mn1C));
            }

            // mask: only touch bits when some are zero (rare path)
            uint32_t allm = mw0.x & mw0.y & mw1.x & mw1.y;
            if (allm != 0xffffffffu) {
#pragma unroll
                for (int nf = 0; nf < 8; nf++) {
                    uint32_t w0 = (nf < 4) ? mw0.x : mw0.y;
                    uint32_t w1 = (nf < 4) ? mw1.x : mw1.y;
                    int sh = ((nf & 3) << 3) + 2 * tig;
                    s[nf][0] = ((w0 >> sh) & 1) ? s[nf][0] : 0.f;
                    s[nf][1] = ((w0 >> (sh + 1)) & 1) ? s[nf][1] : 0.f;
                    s[nf][2] = ((w1 >> sh) & 1) ? s[nf][2] : 0.f;
                    s[nf][3] = ((w1 >> (sh + 1)) & 1) ? s[nf][3] : 0.f;
                }
            }

            float sum0 = 0.f, sum1 = 0.f;
#pragma unroll
            for (int nf = 0; nf < 8; nf++) {
                sum0 += s[nf][0] + s[nf][1];
                sum1 += s[nf][2] + s[nf][3];
            }
#pragma unroll
            for (int off = 1; off <= 2; off <<= 1) {
                sum0 += __shfl_xor_sync(0xffffffffu, sum0, off);
                sum1 += __shfl_xor_sync(0xffffffffu, sum1, off);
            }
            l_i[0] = l_i[0] * cr0 + sum0;
            l_i[1] = l_i[1] * cr1 + sum1;
            m_i[0] = mn0;
            m_i[1] = mn1;
            if (!(cr0 == 1.f && cr1 == 1.f)) {
#pragma unroll
                for (int nf = 0; nf < 8; nf++) {
                    o[nf][0] *= cr0; o[nf][1] *= cr0;
                    o[nf][2] *= cr1; o[nf][3] *= cr1;
                }
            }
        }

        // O += P @ V : C-frag -> A-frag is a pure pack (no shuffles)
#pragma unroll
        for (int g = 0; g < 4; g++) {
            uint32_t pa[4];
            pa[0] = packh2(s[2 * g][0],     s[2 * g][1]);
            pa[1] = packh2(s[2 * g][2],     s[2 * g][3]);
            pa[2] = packh2(s[2 * g + 1][0], s[2 * g + 1][1]);
            pa[3] = packh2(s[2 * g + 1][2], s[2 * g + 1][3]);
#pragma unroll
            for (int np = 0; np < 4; np++) {
                uint32_t b[4];
                ldm4t(b, vBuf + vOff + (uint32_t)(g * (16 * HSTR * 2) + np * 32));
                mma_f16(o[2 * np],     pa, b[0], b[1]);
                mma_f16(o[2 * np + 1], pa, b[2], b[3]);
            }
        }

        __syncthreads();
        if (t + 2 < NT) issueKV((t + 2) * 64, buf);
    }

    // epilogue (fp16 O for the output GEMM)
    float inv0 = (l_i[0] > 0.f) ? (1.f / l_i[0]) : 0.f;
    float inv1 = (l_i[1] > 0.f) ? (1.f / l_i[1]) : 0.f;
    const int r0 = q0 + qb + gid;
#pragma unroll
    for (int nf = 0; nf < 8; nf++) {
        int cc = h * CD + nf * 8 + 2 * tig;
        *(__half2*)&Og[(size_t)r0 * CE + cc] =
            __floats2half2_rn(o[nf][0] * inv0, o[nf][1] * inv0);
        *(__half2*)&Og[(size_t)(r0 + 8) * CE + cc] =
            __floats2half2_rn(o[nf][2] * inv1, o[nf][3] * inv1);
    }
}

// ---------------------------------------------------------------------------

extern "C" void kernel_launch(void* const* d_in, const int* in_sizes, int n_in,
                              void* d_out, int out_size)
{
    const float* query = (const float*)d_in[0];
    const float* key   = (const float*)d_in[1];
    const float* value = (const float*)d_in[2];
    const int*   mask  = (const int*)d_in[3];
    const float* Wq    = (const float*)d_in[4];
    const float* Wk    = (const float*)d_in[5];
    const float* Wv    = (const float*)d_in[6];
    const float* Wo    = (const float*)d_in[7];
    const float* bo    = (const float*)d_in[8];
    float* out = (float*)d_out;

    __half *Qp, *Kp, *Vp, *Op, *Xp, *Wp;
    uint32_t* MBp;
    cudaGetSymbolAddress((void**)&Qp, g_Q);
    cudaGetSymbolAddress((void**)&Kp, g_K);
    cudaGetSymbolAddress((void**)&Vp, g_V);
    cudaGetSymbolAddress((void**)&Op, g_O);
    cudaGetSymbolAddress((void**)&Xp, g_X);
    cudaGetSymbolAddress((void**)&Wp, g_W);
    cudaGetSymbolAddress((void**)&MBp, g_MB);

    const int gemm_smem  = (2 * 128 + 2 * 64) * HSTR * 2;        // 55296
    const int flash_smem = (128 + 2 * 64 + 2 * 64) * HSTR * 2;   // 55296

    cudaFuncSetAttribute(gemm_proj, cudaFuncAttributeMaxDynamicSharedMemorySize, gemm_smem);
    cudaFuncSetAttribute(gemm_out, cudaFuncAttributeMaxDynamicSharedMemorySize, gemm_smem);
    cudaFuncSetAttribute(flash_h, cudaFuncAttributeMaxDynamicSharedMemorySize, flash_smem);

    conv_all<<<dim3(CL * CE / 2048, 1, 7), 256>>>(query, key, value,
                                                  Wq, Wk, Wv, Wo, Xp, Wp);

    pack_mask<<<(CL * CS) / 1024, 256>>>(mask, MBp);

    gemm_proj<<<dim3(CE / 64, CL / 128, 3), 128, gemm_smem>>>(Xp, Wp, Qp, Kp, Vp);

    flash_h<<<dim3(CL / 128, CH), 256, flash_smem>>>(Qp, Kp, Vp, MBp, Op);

    gemm_out<<<dim3(CE / 64, CL / 128), 128, gemm_smem>>>(
        Op, Wp + (size_t)3 * CE * CE, bo, out);
}

// round 9
// speedup vs baseline: 1.9131x; 1.0411x over previous
#include <cuda_runtime.h>
#include <cuda_fp16.h>
#include <cstdint>

#define CL 4096
#define CS 4096
#define CE 768
#define CH 12
#define CD 64
#define HSTR 72   // half-row stride: 144B -> 16B-aligned rows, bank-quad pattern 0,4,..28

static __device__ __host__ constexpr float INV_SCALE = 0.036084391824351614f; // 1/sqrt(768)

// Scratch (no cudaMalloc allowed)
__device__ __half g_Q[CL * CE];
__device__ __half g_K[CS * CE];
__device__ __half g_V[CS * CE];
__device__ __half g_O[CL * CE];
__device__ __half g_X[(size_t)CL * CE * 3];  // fp16 inputs q,k,v
__device__ __half g_W[(size_t)CE * CE * 4];  // fp16 weights Wq,Wk,Wv,Wo
__device__ uint32_t g_MB[(size_t)CL * CS / 32];

// ---------------------------------------------------------------------------
__device__ __forceinline__ uint32_t s2u(const void* p) {
    return (uint32_t)__cvta_generic_to_shared(p);
}
__device__ __forceinline__ void cpa(uint32_t d, const void* s) {
    asm volatile("cp.async.cg.shared.global [%0], [%1], 16;" :: "r"(d), "l"(s));
}
__device__ __forceinline__ void cpcommit() {
    asm volatile("cp.async.commit_group;");
}
template <int N> __device__ __forceinline__ void cpwait() {
    asm volatile("cp.async.wait_group %0;" :: "n"(N));
}

__device__ __forceinline__ void ldm4(uint32_t r[4], uint32_t a) {
    asm volatile("ldmatrix.sync.aligned.m8n8.x4.shared.b16 {%0,%1,%2,%3}, [%4];"
                 : "=r"(r[0]), "=r"(r[1]), "=r"(r[2]), "=r"(r[3]) : "r"(a));
}
__device__ __forceinline__ void ldm4t(uint32_t r[4], uint32_t a) {
    asm volatile("ldmatrix.sync.aligned.m8n8.x4.trans.shared.b16 {%0,%1,%2,%3}, [%4];"
                 : "=r"(r[0]), "=r"(r[1]), "=r"(r[2]), "=r"(r[3]) : "r"(a));
}

__device__ __forceinline__ void mma_f16(float c[4], const uint32_t a[4],
                                        uint32_t b0, uint32_t b1) {
    asm volatile(
        "mma.sync.aligned.m16n8k16.row.col.f32.f16.f16.f32 "
        "{%0,%1,%2,%3}, {%4,%5,%6,%7}, {%8,%9}, {%0,%1,%2,%3};\n"
        : "+f"(c[0]), "+f"(c[1]), "+f"(c[2]), "+f"(c[3])
        : "r"(a[0]), "r"(a[1]), "r"(a[2]), "r"(a[3]), "r"(b0), "r"(b1));
}

__device__ __forceinline__ uint32_t packh2(float lo, float hi) {
    __half2 h = __floats2half2_rn(lo, hi);
    return *reinterpret_cast<uint32_t*>(&h);
}

__device__ __forceinline__ float ex2(float x) {
    float r;
    asm("ex2.approx.f32 %0, %1;" : "=f"(r) : "f"(x));
    return r;
}

// p = 2^(praw*C + mn)   all in half2
__device__ __forceinline__ uint32_t exp2h2(uint32_t praw, __half2 c2, __half2 mn2) {
    __half2 t = __hfma2(*reinterpret_cast<__half2*>(&praw), c2, mn2);
    __half2 e = h2exp2(t);
    return *reinterpret_cast<uint32_t*>(&e);
}

// ---------------------------------------------------------------------------
// Convert inputs + weights to fp16. grid (1536, 1, 7); z<3: inputs, z>=3: weights.
// ---------------------------------------------------------------------------
__global__ __launch_bounds__(256) void conv_all(const float* __restrict__ q,
                                                const float* __restrict__ k,
                                                const float* __restrict__ v,
                                                const float* __restrict__ wq,
                                                const float* __restrict__ wk,
                                                const float* __restrict__ wv,
                                                const float* __restrict__ wo,
                                                __half* __restrict__ X,
                                                __half* __restrict__ W)
{
    const int z = blockIdx.z;
    const float* src;
    __half* dst;
    int nblk;
    if (z < 3) {
        src = (z == 0) ? q : (z == 1) ? k : v;
        dst = X + (size_t)z * CL * CE;
        nblk = CL * CE / 2048;
    } else {
        src = (z == 3) ? wq : (z == 4) ? wk : (z == 5) ? wv : wo;
        dst = W + (size_t)(z - 3) * CE * CE;
        nblk = CE * CE / 2048;
    }
    if (blockIdx.x >= nblk) return;
    size_t i = ((size_t)blockIdx.x * 256 + threadIdx.x) * 8;
    float4 v0 = *(const float4*)&src[i];
    float4 v1 = *(const float4*)&src[i + 4];
    uint32_t h[4];
    h[0] = packh2(v0.x, v0.y);
    h[1] = packh2(v0.z, v0.w);
    h[2] = packh2(v1.x, v1.y);
    h[3] = packh2(v1.z, v1.w);
    *(uint4*)&dst[i] = *(uint4*)h;
}

// ---------------------------------------------------------------------------
// Pack mask to bits, vectorized: bit i of word w = mask[w*32+i] != 0
// ---------------------------------------------------------------------------
__global__ __launch_bounds__(256) void pack_mask(const int* __restrict__ m,
                                                 uint32_t* __restrict__ mb) {
    __shared__ uint32_t nib[256];
    int t = threadIdx.x;
    size_t base = (size_t)blockIdx.x * 1024 + (size_t)t * 4;
    int4 v = *(const int4*)&m[base];
    nib[t] = (v.x ? 1u : 0u) | (v.y ? 2u : 0u) | (v.z ? 4u : 0u) | (v.w ? 8u : 0u);
    __syncthreads();
    if (t < 32) {
        uint32_t w = 0;
#pragma unroll
        for (int j = 0; j < 8; j++) w |= nib[t * 8 + j] << (4 * j);
        mb[(size_t)blockIdx.x * 32 + t] = w;
    }
}

// ---------------------------------------------------------------------------
// fp16 GEMM core, cp.async double-buffered + ldmatrix. 128 thr (4 warps),
// CTA tile 128x64, warp 32x64, k-step 64. A[M,768] @ W[768,64-slice].
// ---------------------------------------------------------------------------
__device__ __forceinline__ void gemm_body(const __half* __restrict__ A,
                                          const __half* __restrict__ W,
                                          const float* __restrict__ bias,
                                          float* __restrict__ Cf,
                                          __half* __restrict__ Ch,
                                          int m0, int n0, char* sgc)
{
    __half* smA = (__half*)sgc;             // 2 x 128 x HSTR
    __half* smW = smA + 2 * 128 * HSTR;     // 2 x 64 x HSTR

    const int tid = threadIdx.x;
    const int wid = tid >> 5;
    const int ln  = tid & 31;
    const int gid = ln >> 2;
    const int tig = ln & 3;
    const int qb  = wid * 32;

    const uint32_t aoff0 = (uint32_t)(((qb + (ln & 15)) * HSTR + (ln >> 4) * 8) << 1);
    const uint32_t aoff1 = aoff0 + (16 * HSTR << 1);
    const uint32_t woff  = (uint32_t)(((((ln & 7) + ((ln >> 3) & 1) * 8) * HSTR) + (ln >> 4) * 8) << 1);
    const uint32_t smAu = s2u(smA);
    const uint32_t smWu = s2u(smW);

    auto issue = [&](int k0, int b) {
        __half* dA = smA + b * 128 * HSTR;
        __half* dW = smW + b * 64 * HSTR;
#pragma unroll
        for (int i = 0; i < 8; i++) {
            int lin = tid + i * 128;
            int row = lin >> 3, ch = (lin & 7) * 8;
            cpa(s2u(&dA[row * HSTR + ch]), &A[(size_t)(m0 + row) * CE + k0 + ch]);
        }
#pragma unroll
        for (int i = 0; i < 4; i++) {
            int lin = tid + i * 128;
            int kr = lin >> 3, ch = (lin & 7) * 8;
            cpa(s2u(&dW[kr * HSTR + ch]), &W[(size_t)(k0 + kr) * CE + n0 + ch]);
        }
        cpcommit();
    };

    float c[2][8][4];
#pragma unroll
    for (int m = 0; m < 2; m++)
#pragma unroll
        for (int nf = 0; nf < 8; nf++)
#pragma unroll
            for (int j = 0; j < 4; j++) c[m][nf][j] = 0.f;

    const int NS = CE / 64;  // 12
    issue(0, 0);
    issue(64, 1);

    for (int ks = 0; ks < NS; ks++) {
        const int buf = ks & 1;
        if (ks < NS - 1) cpwait<1>(); else cpwait<0>();
        __syncthreads();

        const uint32_t aBuf = smAu + (uint32_t)(buf * 128 * HSTR * 2);
        const uint32_t wBuf = smWu + (uint32_t)(buf * 64 * HSTR * 2);

#pragma unroll
        for (int g = 0; g < 4; g++) {
            uint32_t a0[4], a1[4];
            ldm4(a0, aBuf + aoff0 + g * 32);
            ldm4(a1, aBuf + aoff1 + g * 32);
#pragma unroll
            for (int np = 0; np < 4; np++) {
                uint32_t b[4];
                ldm4t(b, wBuf + woff + (uint32_t)(g * (16 * HSTR * 2) + np * 32));
                mma_f16(c[0][2 * np],     a0, b[0], b[1]);
                mma_f16(c[0][2 * np + 1], a0, b[2], b[3]);
                mma_f16(c[1][2 * np],     a1, b[0], b[1]);
                mma_f16(c[1][2 * np + 1], a1, b[2], b[3]);
            }
        }
        __syncthreads();
        if (ks + 2 < NS) issue((ks + 2) * 64, buf);
    }

#pragma unroll
    for (int m = 0; m < 2; m++) {
        int r0 = m0 + qb + m * 16 + gid;
        int r1 = r0 + 8;
#pragma unroll
        for (int nf = 0; nf < 8; nf++) {
            int n = n0 + nf * 8 + 2 * tig;
            if (Ch) {
                *(__half2*)&Ch[(size_t)r0 * CE + n] =
                    __floats2half2_rn(c[m][nf][0], c[m][nf][1]);
                *(__half2*)&Ch[(size_t)r1 * CE + n] =
                    __floats2half2_rn(c[m][nf][2], c[m][nf][3]);
            } else {
                float b0v = bias[n], b1v = bias[n + 1];
                *(float2*)&Cf[(size_t)r0 * CE + n] =
                    make_float2(c[m][nf][0] + b0v, c[m][nf][1] + b1v);
                *(float2*)&Cf[(size_t)r1 * CE + n] =
                    make_float2(c[m][nf][2] + b0v, c[m][nf][3] + b1v);
            }
        }
    }
}

__global__ __launch_bounds__(128) void gemm_proj(const __half* __restrict__ X,
                                                 const __half* __restrict__ W,
                                                 __half* __restrict__ Qp,
                                                 __half* __restrict__ Kp,
                                                 __half* __restrict__ Vp)
{
    extern __shared__ char sgc[];
    const int z = blockIdx.z;
    const __half* A = X + (size_t)z * CL * CE;
    const __half* Wz = W + (size_t)z * CE * CE;
    __half* C = (z == 0) ? Qp : (z == 1) ? Kp : Vp;
    gemm_body(A, Wz, nullptr, nullptr, C, blockIdx.y * 128, blockIdx.x * 64, sgc);
}

__global__ __launch_bounds__(128) void gemm_out(const __half* __restrict__ A,
                                                const __half* __restrict__ W,
                                                const float* __restrict__ bias,
                                                float* __restrict__ C)
{
    extern __shared__ char sgc[];
    gemm_body(A, W, bias, C, nullptr, blockIdx.y * 128, blockIdx.x * 64, sgc);
}

// ---------------------------------------------------------------------------
// Flash attention fp16. 3-stage cp.async ring with ONE __syncthreads per tile,
// fp16 exp2 softmax, tensor-core row sums, zero-copy P.
// Block = (128 q, head), 8 warps x 16 rows.
// ---------------------------------------------------------------------------
__global__ __launch_bounds__(256, 2) void flash_h(const __half* __restrict__ Qg,
                                                  const __half* __restrict__ Kg,
                                                  const __half* __restrict__ Vg,
                                                  const uint32_t* __restrict__ MBg,
                                                  __half* __restrict__ Og)
{
    extern __shared__ char smc[];
    __half* Qs = (__half*)smc;              // 128 x HSTR
    __half* Ks = Qs + 128 * HSTR;           // 3 x 64 x HSTR
    __half* Vs = Ks + 3 * 64 * HSTR;        // 3 x 64 x HSTR

    const uint2* MB2 = (const uint2*)MBg;
    const float CEXP = 0.05205889686f;      // INV_SCALE * log2(e)
    const uint32_t ONES2 = 0x3C003C00u;     // half2(1,1)

    const int h  = blockIdx.y;
    const int q0 = blockIdx.x * 128;
    const int tid = threadIdx.x;
    const int wid = tid >> 5;
    const int ln  = tid & 31;
    const int gid = ln >> 2;
    const int tig = ln & 3;
    const int qb = wid * 16;

    const uint32_t qBase = s2u(Qs) + (uint32_t)(((qb + (ln & 15)) * HSTR + (ln >> 4) * 8) << 1);
    const uint32_t kOff  = (uint32_t)(((((ln & 7) + ((ln >> 4) & 1) * 8) * HSTR) + ((ln >> 3) & 1) * 8) << 1);
    const uint32_t vOff  = (uint32_t)(((((ln & 7) + ((ln >> 3) & 1) * 8) * HSTR) + (ln >> 4) * 8) << 1);
    const uint32_t KsU = s2u(Ks);
    const uint32_t VsU = s2u(Vs);

    auto issueKV = [&](int k0, int b) {
        __half* dK = Ks + b * 64 * HSTR;
        __half* dV = Vs + b * 64 * HSTR;
#pragma unroll
        for (int i = 0; i < 2; i++) {
            int lin = tid + i * 256;
            int row = lin >> 3, ch = (lin & 7) * 8;
            cpa(s2u(&dK[row * HSTR + ch]), &Kg[(size_t)(k0 + row) * CE + h * CD + ch]);
            cpa(s2u(&dV[row * HSTR + ch]), &Vg[(size_t)(k0 + row) * CE + h * CD + ch]);
        }
        cpcommit();
    };

    // prologue: Q joins group 0; stages 0 and 1 filled
#pragma unroll
    for (int i = 0; i < 4; i++) {
        int lin = tid + i * 256;
        int row = lin >> 3, ch = (lin & 7) * 8;
        cpa(s2u(&Qs[row * HSTR + ch]), &Qg[(size_t)(q0 + row) * CE + h * CD + ch]);
    }
    issueKV(0, 0);
    issueKV(64, 1);

    float m_i[2] = {-1e30f, -1e30f};   // raw (unscaled) units
    float l_i[2] = {0.f, 0.f};
    float o[8][4];
#pragma unroll
    for (int nf = 0; nf < 8; nf++)
#pragma unroll
        for (int j = 0; j < 4; j++) o[nf][j] = 0.f;

    const int mrow = q0 + qb + gid;
    const int NT = CS / 64;  // 64
    int buf = 0, nbuf = 2;   // buf = t%3 ; nbuf = (t+2)%3

    for (int t = 0; t < NT; t++) {
        uint2 mw0 = MB2[(size_t)mrow * 64 + t];
        uint2 mw1 = MB2[(size_t)(mrow + 8) * 64 + t];

        // tile t's group retired (tile t+1's may still be in flight)
        if (t < NT - 1) cpwait<1>(); else cpwait<0>();
        __syncthreads();   // all warps done reading buffer (t-2)%3 == nbuf
        if (t + 2 < NT) issueKV((t + 2) * 64, nbuf);

        const uint32_t kBuf = KsU + (uint32_t)(buf * 64 * HSTR * 2);
        const uint32_t vBuf = VsU + (uint32_t)(buf * 64 * HSTR * 2);

        // S = Q @ K^T  (warp: 16 x 64), raw units
        float s[8][4];
#pragma unroll
        for (int nf = 0; nf < 8; nf++)
#pragma unroll
            for (int j = 0; j < 4; j++) s[nf][j] = 0.f;

#pragma unroll
        for (int g = 0; g < 4; g++) {
            uint32_t a[4];
            ldm4(a, qBase + g * 32);
#pragma unroll
            for (int np = 0; np < 4; np++) {
                uint32_t b[4];
                ldm4(b, kBuf + kOff + (uint32_t)(np * (16 * HSTR * 2) + g * 32));
                mma_f16(s[2 * np],     a, b[0], b[1]);
                mma_f16(s[2 * np + 1], a, b[2], b[3]);
            }
        }

        // online softmax: fp16 exp2, tensor-core row sum
        uint32_t ph0[8], ph1[8];
        float cr0, cr1;
        {
            float mx0 = -1e30f, mx1 = -1e30f;
#pragma unroll
            for (int nf = 0; nf < 8; nf++) {
                mx0 = fmaxf(mx0, fmaxf(s[nf][0], s[nf][1]));
                mx1 = fmaxf(mx1, fmaxf(s[nf][2], s[nf][3]));
            }
#pragma unroll
            for (int off = 1; off <= 2; off <<= 1) {
                mx0 = fmaxf(mx0, __shfl_xor_sync(0xffffffffu, mx0, off));
                mx1 = fmaxf(mx1, __shfl_xor_sync(0xffffffffu, mx1, off));
            }
            float mn0 = fmaxf(m_i[0], mx0);
            float mn1 = fmaxf(m_i[1], mx1);
            cr0 = ex2((m_i[0] - mn0) * CEXP);
            cr1 = ex2((m_i[1] - mn1) * CEXP);
            m_i[0] = mn0;
            m_i[1] = mn1;

            const __half2 C2  = __float2half2_rn(CEXP);
            const __half2 B0  = __float2half2_rn(-mn0 * CEXP);
            const __half2 B1  = __float2half2_rn(-mn1 * CEXP);

#pragma unroll
            for (int nf = 0; nf < 8; nf++) {
                ph0[nf] = exp2h2(packh2(s[nf][0], s[nf][1]), C2, B0);
                ph1[nf] = exp2h2(packh2(s[nf][2], s[nf][3]), C2, B1);
            }

            // mask: rare path — zero halves via bit masks
            uint32_t allm = mw0.x & mw0.y & mw1.x & mw1.y;
            if (allm != 0xffffffffu) {
#pragma unroll
                for (int nf = 0; nf < 8; nf++) {
                    uint32_t w0 = (nf < 4) ? mw0.x : mw0.y;
                    uint32_t w1 = (nf < 4) ? mw1.x : mw1.y;
                    int sh = ((nf & 3) << 3) + 2 * tig;
                    uint32_t k0m = (((w0 >> sh) & 1) ? 0x0000FFFFu : 0u) |
                                   (((w0 >> (sh + 1)) & 1) ? 0xFFFF0000u : 0u);
                    uint32_t k1m = (((w1 >> sh) & 1) ? 0x0000FFFFu : 0u) |
                                   (((w1 >> (sh + 1)) & 1) ? 0xFFFF0000u : 0u);
                    ph0[nf] &= k0m;
                    ph1[nf] &= k1m;
                }
            }

            // row sums on the tensor pipe: P @ ones
            float rs[4] = {0.f, 0.f, 0.f, 0.f};
#pragma unroll
            for (int g = 0; g < 4; g++) {
                uint32_t pa[4] = {ph0[2 * g], ph1[2 * g], ph0[2 * g + 1], ph1[2 * g + 1]};
                mma_f16(rs, pa, ONES2, ONES2);
            }
            l_i[0] = l_i[0] * cr0 + rs[0];
            l_i[1] = l_i[1] * cr1 + rs[2];

            if (!(cr0 == 1.f && cr1 == 1.f)) {
#pragma unroll
                for (int nf = 0; nf < 8; nf++) {
                    o[nf][0] *= cr0; o[nf][1] *= cr0;
                    o[nf][2] *= cr1; o[nf][3] *= cr1;
                }
            }
        }

        // O += P @ V
#pragma unroll
        for (int g = 0; g < 4; g++) {
            uint32_t pa[4] = {ph0[2 * g], ph1[2 * g], ph0[2 * g + 1], ph1[2 * g + 1]};
#pragma unroll
            for (int np = 0; np < 4; np++) {
                uint32_t b[4];
                ldm4t(b, vBuf + vOff + (uint32_t)(g * (16 * HSTR * 2) + np * 32));
                mma_f16(o[2 * np],     pa, b[0], b[1]);
                mma_f16(o[2 * np + 1], pa, b[2], b[3]);
            }
        }

        buf = (buf == 2) ? 0 : buf + 1;
        nbuf = (nbuf == 2) ? 0 : nbuf + 1;
    }

    // epilogue (fp16 O for the output GEMM)
    float inv0 = (l_i[0] > 0.f) ? (1.f / l_i[0]) : 0.f;
    float inv1 = (l_i[1] > 0.f) ? (1.f / l_i[1]) : 0.f;
    const int r0 = q0 + qb + gid;
#pragma unroll
    for (int nf = 0; nf < 8; nf++) {
        int cc = h * CD + nf * 8 + 2 * tig;
        *(__half2*)&Og[(size_t)r0 * CE + cc] =
            __floats2half2_rn(o[nf][0] * inv0, o[nf][1] * inv0);
        *(__half2*)&Og[(size_t)(r0 + 8) * CE + cc] =
            __floats2half2_rn(o[nf][2] * inv1, o[nf][3] * inv1);
    }
}

// ---------------------------------------------------------------------------

extern "C" void kernel_launch(void* const* d_in, const int* in_sizes, int n_in,
                              void* d_out, int out_size)
{
    const float* query = (const float*)d_in[0];
    const float* key   = (const float*)d_in[1];
    const float* value = (const float*)d_in[2];
    const int*   mask  = (const int*)d_in[3];
    const float* Wq    = (const float*)d_in[4];
    const float* Wk    = (const float*)d_in[5];
    const float* Wv    = (const float*)d_in[6];
    const float* Wo    = (const float*)d_in[7];
    const float* bo    = (const float*)d_in[8];
    float* out = (float*)d_out;

    __half *Qp, *Kp, *Vp, *Op, *Xp, *Wp;
    uint32_t* MBp;
    cudaGetSymbolAddress((void**)&Qp, g_Q);
    cudaGetSymbolAddress((void**)&Kp, g_K);
    cudaGetSymbolAddress((void**)&Vp, g_V);
    cudaGetSymbolAddress((void**)&Op, g_O);
    cudaGetSymbolAddress((void**)&Xp, g_X);
    cudaGetSymbolAddress((void**)&Wp, g_W);
    cudaGetSymbolAddress((void**)&MBp, g_MB);

    const int gemm_smem  = (2 * 128 + 2 * 64) * HSTR * 2;        // 55296
    const int flash_smem = (128 + 3 * 64 + 3 * 64) * HSTR * 2;   // 73728

    cudaFuncSetAttribute(gemm_proj, cudaFuncAttributeMaxDynamicSharedMemorySize, gemm_smem);
    cudaFuncSetAttribute(gemm_out, cudaFuncAttributeMaxDynamicSharedMemorySize, gemm_smem);
    cudaFuncSetAttribute(flash_h, cudaFuncAttributeMaxDynamicSharedMemorySize, flash_smem);

    conv_all<<<dim3(CL * CE / 2048, 1, 7), 256>>>(query, key, value,
                                                  Wq, Wk, Wv, Wo, Xp, Wp);

    pack_mask<<<(CL * CS) / 1024, 256>>>(mask, MBp);

    gemm_proj<<<dim3(CE / 64, CL / 128, 3), 128, gemm_smem>>>(Xp, Wp, Qp, Kp, Vp);

    flash_h<<<dim3(CL / 128, CH), 256, flash_smem>>>(Qp, Kp, Vp, MBp, Op);

    gemm_out<<<dim3(CE / 64, CL / 128), 128, gemm_smem>>>(
        Op, Wp + (size_t)3 * CE * CE, bo, out);
}